// round 1
// baseline (speedup 1.0000x reference)
#include <cuda_runtime.h>
#include <cstdint>

// Problem constants (fixed by the reference)
#define NA   50000
#define NB   200000
#define CA   256
#define CB   128
#define CX   384      // concat width
#define CO   256      // output channels
#define KT   8
#define MT   100000
#define KC   27
#define MC   120000
#define BN_EPS 1e-5f

// Intermediate concat buffer x = [xa_bn | feats_b], row stride CX.
// Columns [0,256) first hold the transpose-conv accumulator, then BN+ReLU in place.
__device__ float g_x[(size_t)NB * CX];

// ---------------------------------------------------------------------------
// packed f32x2 helpers (PTX-only instruction on sm_103a; ptxas won't auto-fuse)
// ---------------------------------------------------------------------------
__device__ __forceinline__ unsigned long long pack2(float lo, float hi) {
    unsigned long long r;
    asm("mov.b64 %0, {%1, %2};" : "=l"(r)
        : "r"(__float_as_uint(lo)), "r"(__float_as_uint(hi)));
    return r;
}
__device__ __forceinline__ void ffma2(unsigned long long& c,
                                      unsigned long long a,
                                      unsigned long long b) {
    asm("fma.rn.f32x2 %0, %1, %2, %0;" : "+l"(c) : "l"(a), "l"(b));
}

union F4U { float4 f4; unsigned long long u[2]; float f[4]; };

// ---------------------------------------------------------------------------
// init: g_x[:, 0:256] = 0 ; g_x[:, 256:384] = feats_b   (one row per block)
// ---------------------------------------------------------------------------
__global__ void init_x_kernel(const float* __restrict__ feats_b) {
    int row = blockIdx.x;
    int t = threadIdx.x;              // 128 threads, 96 active (CX/4)
    if (t >= CX / 4) return;
    float4* xp = reinterpret_cast<float4*>(g_x + (size_t)row * CX);
    if (t < CA / 4) {
        xp[t] = make_float4(0.f, 0.f, 0.f, 0.f);
    } else {
        const float4* fb = reinterpret_cast<const float4*>(feats_b + (size_t)row * CB);
        xp[t] = fb[t - CA / 4];
    }
}

__global__ void zero_f4_kernel(float* __restrict__ p, int n4) {
    int i = blockIdx.x * blockDim.x + threadIdx.x;
    if (i < n4) reinterpret_cast<float4*>(p)[i] = make_float4(0.f, 0.f, 0.f, 0.f);
}

// ---------------------------------------------------------------------------
// Gather-GEMM-scatter for one sparse conv.
//   feats: [*, CIN] (row stride == CIN), W: [K][CIN][CO]
//   out[out_map[z][m]][:] += feats[in_map[z][m]][:] @ W[z]
// Block tile: 64 rows (pairs) x 128 out-channels. 256 threads, 4x8 per thread.
// ---------------------------------------------------------------------------
template <int CIN, int OUT_STRIDE, bool SRC_GX, bool DST_GX>
__global__ void __launch_bounds__(256)
spconv_gemm_kernel(const float* __restrict__ feats_in,
                   const float* __restrict__ W,
                   const int* __restrict__ in_map,
                   const int* __restrict__ out_map,
                   float* __restrict__ out_param,
                   int M) {
    __shared__ float As[16][68];    // [k][row], padded
    __shared__ float Bs[16][128];   // [k][col]

    const float* feats = SRC_GX ? (const float*)g_x : feats_in;
    float* out = DST_GX ? (float*)g_x : out_param;

    const int tid = threadIdx.x;
    const int z  = blockIdx.z;
    const int m0 = blockIdx.x * 64;
    const int n0 = blockIdx.y * 128;

    // ---- A gather assignment: one float4 per thread per k-chunk
    const int lrow = tid >> 2;          // 0..63
    const int lseg = tid & 3;           // 0..3 -> 4 floats each
    const int mA = m0 + lrow;
    long long gA = -1;
    if (mA < M) gA = (long long)in_map[(size_t)z * M + mA] * CIN;

    // ---- B load assignment: two float4 per thread (rows brow, brow+8)
    const int brow = tid >> 5;          // 0..7
    const int bcol = (tid & 31) * 4;    // 0..124

    // ---- compute assignment: 4 rows x (4 + 4) cols
    const int r0 = (tid >> 4) * 4;      // 0..60
    const int c0 = (tid & 15) * 4;      // 0..60 ; second half at c0+64

    unsigned long long acc[4][4];
    #pragma unroll
    for (int i = 0; i < 4; ++i)
        #pragma unroll
        for (int j = 0; j < 4; ++j) acc[i][j] = 0ull;

    for (int kk0 = 0; kk0 < CIN; kk0 += 16) {
        // gather A chunk (before sync so the load overlaps prior compute tail)
        float4 av = make_float4(0.f, 0.f, 0.f, 0.f);
        if (gA >= 0)
            av = *reinterpret_cast<const float4*>(feats + gA + kk0 + lseg * 4);
        const float* wp = W + ((size_t)z * CIN + kk0) * CO + n0;
        float4 bv0 = *reinterpret_cast<const float4*>(wp + (size_t)brow * CO + bcol);
        float4 bv1 = *reinterpret_cast<const float4*>(wp + (size_t)(brow + 8) * CO + bcol);

        __syncthreads();
        As[lseg * 4 + 0][lrow] = av.x;
        As[lseg * 4 + 1][lrow] = av.y;
        As[lseg * 4 + 2][lrow] = av.z;
        As[lseg * 4 + 3][lrow] = av.w;
        *reinterpret_cast<float4*>(&Bs[brow][bcol])     = bv0;
        *reinterpret_cast<float4*>(&Bs[brow + 8][bcol]) = bv1;
        __syncthreads();

        #pragma unroll
        for (int kk = 0; kk < 16; ++kk) {
            F4U a4; a4.f4 = *reinterpret_cast<const float4*>(&As[kk][r0]);
            F4U bl; bl.f4 = *reinterpret_cast<const float4*>(&Bs[kk][c0]);
            F4U bh; bh.f4 = *reinterpret_cast<const float4*>(&Bs[kk][c0 + 64]);
            #pragma unroll
            for (int i = 0; i < 4; ++i) {
                unsigned long long ai = pack2(a4.f[i], a4.f[i]);
                ffma2(acc[i][0], ai, bl.u[0]);
                ffma2(acc[i][1], ai, bl.u[1]);
                ffma2(acc[i][2], ai, bh.u[0]);
                ffma2(acc[i][3], ai, bh.u[1]);
            }
        }
    }

    // ---- scatter-add
    #pragma unroll
    for (int i = 0; i < 4; ++i) {
        int mm = m0 + r0 + i;
        if (mm < M) {
            int o = out_map[(size_t)z * M + mm];
            float* p = out + (size_t)o * OUT_STRIDE + n0;
            F4U v0, v1;
            v0.u[0] = acc[i][0]; v0.u[1] = acc[i][1];
            v1.u[0] = acc[i][2]; v1.u[1] = acc[i][3];
            atomicAdd(p + c0 + 0, v0.f[0]);
            atomicAdd(p + c0 + 1, v0.f[1]);
            atomicAdd(p + c0 + 2, v0.f[2]);
            atomicAdd(p + c0 + 3, v0.f[3]);
            atomicAdd(p + c0 + 64, v1.f[0]);
            atomicAdd(p + c0 + 65, v1.f[1]);
            atomicAdd(p + c0 + 66, v1.f[2]);
            atomicAdd(p + c0 + 67, v1.f[3]);
        }
    }
}

// ---------------------------------------------------------------------------
// BN (eval) + ReLU, in place. STRIDE distinguishes g_x (384) vs out (256).
// ---------------------------------------------------------------------------
template <int STRIDE, bool ON_GX>
__global__ void bn_relu_kernel(float* __restrict__ buf,
                               const float* __restrict__ gamma,
                               const float* __restrict__ beta,
                               const float* __restrict__ mean,
                               const float* __restrict__ var) {
    int c = threadIdx.x;   // 256 channels
    float s  = gamma[c] * rsqrtf(var[c] + BN_EPS);
    float sh = beta[c] - mean[c] * s;
    float* base = ON_GX ? (float*)g_x : buf;
    for (int row = blockIdx.x; row < NB; row += gridDim.x) {
        size_t idx = (size_t)row * STRIDE + c;
        base[idx] = fmaxf(fmaf(base[idx], s, sh), 0.f);
    }
}

// ---------------------------------------------------------------------------
extern "C" void kernel_launch(void* const* d_in, const int* in_sizes, int n_in,
                              void* d_out, int out_size) {
    const float* feats_a    = (const float*)d_in[0];
    const float* feats_b    = (const float*)d_in[1];
    const float* W_t        = (const float*)d_in[2];
    const float* bn_t_gamma = (const float*)d_in[3];
    const float* bn_t_beta  = (const float*)d_in[4];
    const float* bn_t_mean  = (const float*)d_in[5];
    const float* bn_t_var   = (const float*)d_in[6];
    const float* W_c        = (const float*)d_in[7];
    const float* bn_c_gamma = (const float*)d_in[8];
    const float* bn_c_beta  = (const float*)d_in[9];
    const float* bn_c_mean  = (const float*)d_in[10];
    const float* bn_c_var   = (const float*)d_in[11];
    const int*   in_map_t   = (const int*)d_in[12];
    const int*   out_map_t  = (const int*)d_in[13];
    const int*   in_map_c   = (const int*)d_in[14];
    const int*   out_map_c  = (const int*)d_in[15];
    float* out = (float*)d_out;

    // 1) init concat buffer (zero xa region, copy skip feats) + zero output accum
    init_x_kernel<<<NB, 128>>>(feats_b);
    {
        int n4 = (int)((size_t)NB * CO / 4);
        zero_f4_kernel<<<(n4 + 255) / 256, 256>>>(out, n4);
    }

    // 2) transpose conv: feats_a @ W_t  ->  g_x[:, 0:256]  (scatter-add)
    {
        dim3 grid((MT + 63) / 64, CO / 128, KT);
        spconv_gemm_kernel<CA, CX, false, true>
            <<<grid, 256>>>(feats_a, W_t, in_map_t, out_map_t, nullptr, MT);
    }

    // 3) BN + ReLU on xa (in g_x)
    bn_relu_kernel<CX, true><<<2048, 256>>>(nullptr, bn_t_gamma, bn_t_beta,
                                            bn_t_mean, bn_t_var);

    // 4) 3x3x3 conv: g_x(384) @ W_c -> out (scatter-add)
    {
        dim3 grid((MC + 63) / 64, CO / 128, KC);
        spconv_gemm_kernel<CX, CO, true, false>
            <<<grid, 256>>>(nullptr, W_c, in_map_c, out_map_c, out, MC);
    }

    // 5) BN + ReLU on output
    bn_relu_kernel<CO, false><<<2048, 256>>>(out, bn_c_gamma, bn_c_beta,
                                             bn_c_mean, bn_c_var);
}

// round 6
// speedup vs baseline: 1.8299x; 1.8299x over previous
#include <cuda_runtime.h>
#include <cuda_bf16.h>
#include <cstdint>

// Problem constants
#define NA   50000
#define NB   200000
#define CA   256
#define CB   128
#define CX   384
#define CO   256
#define KT   8
#define MT   100000
#define KC   27
#define MC   120000
#define BN_EPS 1e-5f

// Device-resident buffers
__device__ float g_x[(size_t)NB * CX];                       // concat buffer [NB,384]
__device__ __nv_bfloat16 g_Wt_hi[(size_t)KT * CO * CA];      // W_t transposed [z][n][k]
__device__ __nv_bfloat16 g_Wt_lo[(size_t)KT * CO * CA];
__device__ __nv_bfloat16 g_Wc_hi[(size_t)KC * CO * CX];      // W_c transposed [z][n][k]
__device__ __nv_bfloat16 g_Wc_lo[(size_t)KC * CO * CX];

// ===========================================================================
// PTX helpers (generic PTX only — tcgen05 is unavailable at compute_103)
// ===========================================================================
__device__ __forceinline__ uint32_t smem_to_u32(const void* p) {
    uint32_t a;
    asm("{ .reg .u64 t; cvta.to.shared.u64 t, %1; cvt.u32.u64 %0, t; }" : "=r"(a) : "l"(p));
    return a;
}

#define CP_ASYNC_16(dst_u32, src_ptr) \
    asm volatile("cp.async.cg.shared.global [%0], [%1], 16;" \
                 :: "r"(dst_u32), "l"(src_ptr) : "memory")
#define CP_ASYNC_COMMIT() asm volatile("cp.async.commit_group;" ::: "memory")
#define CP_ASYNC_WAIT0()  asm volatile("cp.async.wait_group 0;" ::: "memory")

#define LDSM_X4(r0, r1, r2, r3, addr) \
    asm volatile("ldmatrix.sync.aligned.m8n8.x4.shared.b16 {%0,%1,%2,%3}, [%4];" \
                 : "=r"(r0), "=r"(r1), "=r"(r2), "=r"(r3) : "r"(addr))

#define MMA_BF16(d, a, b) \
    asm volatile("mma.sync.aligned.m16n8k16.row.col.f32.bf16.bf16.f32 " \
                 "{%0,%1,%2,%3}, {%4,%5,%6,%7}, {%8,%9}, {%0,%1,%2,%3};" \
                 : "+f"((d)[0]), "+f"((d)[1]), "+f"((d)[2]), "+f"((d)[3]) \
                 : "r"((a)[0]), "r"((a)[1]), "r"((a)[2]), "r"((a)[3]), \
                   "r"((b)[0]), "r"((b)[1]))

__device__ __forceinline__ void red_add_v2(float* p, float a, float b) {
    asm volatile("red.global.add.v2.f32 [%0], {%1, %2};"
                 :: "l"(p), "f"(a), "f"(b) : "memory");
}

// Split fp32 pair into packed bf16 hi / lo
__device__ __forceinline__ void split2(float x, float y, uint32_t& h, uint32_t& l) {
    __nv_bfloat162 hh = __float22bfloat162_rn(make_float2(x, y));
    float2 hf = __bfloat1622float2(hh);
    __nv_bfloat162 ll = __float22bfloat162_rn(make_float2(x - hf.x, y - hf.y));
    h = *reinterpret_cast<uint32_t*>(&hh);
    l = *reinterpret_cast<uint32_t*>(&ll);
}

// ===========================================================================
// Prep: transpose W [K][CIN][CO] -> [K][CO][CIN] and split into bf16 hi/lo
// ===========================================================================
template <int CIN>
__global__ void prep_w_kernel(const float* __restrict__ W,
                              __nv_bfloat16* __restrict__ hi,
                              __nv_bfloat16* __restrict__ lo) {
    __shared__ float t[32][33];
    const int z = blockIdx.z;
    const int k0 = blockIdx.y * 32, n0 = blockIdx.x * 32;
    const int tx = threadIdx.x, ty = threadIdx.y;   // (32, 8)
    #pragma unroll
    for (int i = 0; i < 4; ++i) {
        int k = k0 + ty + i * 8;
        t[ty + i * 8][tx] = W[((size_t)z * CIN + k) * CO + n0 + tx];
    }
    __syncthreads();
    #pragma unroll
    for (int i = 0; i < 4; ++i) {
        int n = n0 + ty + i * 8;
        float v = t[tx][ty + i * 8];
        __nv_bfloat16 h = __float2bfloat16(v);
        float r = v - __bfloat162float(h);
        size_t o = ((size_t)z * CO + n) * CIN + k0 + tx;
        hi[o] = h;
        lo[o] = __float2bfloat16(r);
    }
}

// ===========================================================================
// init: g_x[:,0:256]=0 ; g_x[:,256:384]=feats_b ; zero out
// ===========================================================================
__global__ void init_x_kernel(const float* __restrict__ feats_b) {
    int row = blockIdx.x;
    int t = threadIdx.x;
    if (t >= CX / 4) return;
    float4* xp = reinterpret_cast<float4*>(g_x + (size_t)row * CX);
    if (t < CA / 4) {
        xp[t] = make_float4(0.f, 0.f, 0.f, 0.f);
    } else {
        const float4* fb = reinterpret_cast<const float4*>(feats_b + (size_t)row * CB);
        xp[t] = fb[t - CA / 4];
    }
}

__global__ void zero_f4_kernel(float* __restrict__ p, int n4) {
    int i = blockIdx.x * blockDim.x + threadIdx.x;
    if (i < n4) reinterpret_cast<float4*>(p)[i] = make_float4(0.f, 0.f, 0.f, 0.f);
}

// ===========================================================================
// Sparse conv: gather(A fp32 -> bf16 hi/lo) + cp.async(B) -> mma.sync -> red
// CTA tile: 128 pairs x 128 out-ch. 8 warps (4 M x 2 N), warp tile 32x64.
// K chunks of 32, double-buffered SMEM, 80B row stride (conflict-free LDSM).
// SMEM per buffer: Ah 10240 | Al 10240 | Bh 10240 | Bl 10240  (40960 B)
// ===========================================================================
#define SA        40              // bf16 elems per smem row (80 bytes)
#define OFF_AH    0
#define OFF_AL    10240
#define OFF_BH    20480
#define OFF_BL    30720
#define BUF_SZ    40960
#define SMEM_TOTAL (2 * BUF_SZ)

template <int CIN, int OUT_STRIDE, bool SRC_GX, bool DST_GX>
__global__ void __launch_bounds__(256)
spconv_mma_kernel(const float* __restrict__ feats_in,
                  const __nv_bfloat16* __restrict__ Whi,
                  const __nv_bfloat16* __restrict__ Wlo,
                  const int* __restrict__ in_map,
                  const int* __restrict__ out_map,
                  float* __restrict__ out_param,
                  int M) {
    extern __shared__ char smc[];
    const uint32_t sb = smem_to_u32(smc);

    const float* feats = SRC_GX ? (const float*)g_x : feats_in;
    float* outb = DST_GX ? (float*)g_x : out_param;

    const int tid  = threadIdx.x;
    const int lane = tid & 31;
    const int w    = tid >> 5;
    const int wm   = w & 3;          // 0..3 (M groups of 32)
    const int wn   = w >> 2;         // 0..1 (N groups of 64)

    const int z  = blockIdx.z;
    const int m0 = blockIdx.x * 128;
    const int n0 = blockIdx.y * 128;
    const size_t zM = (size_t)z * M;

    // ---- A gather assignment: thread -> (row, 16-float segment)
    const int ar   = tid >> 1;       // 0..127
    const int aseg = tid & 1;        // 0..1
    const int am   = m0 + ar;
    long long gA = -1;
    if (am < M) gA = (long long)in_map[zM + am] * CIN;

    // ---- B cp.async assignment: thread -> (n row, 16-bf16 segment)
    const int br   = tid >> 1;
    const int bseg = tid & 1;
    const __nv_bfloat16* srcBh = Whi + ((size_t)z * CO + n0 + br) * CIN + bseg * 16;
    const __nv_bfloat16* srcBl = Wlo + ((size_t)z * CO + n0 + br) * CIN + bseg * 16;
    const uint32_t dstB = sb + (uint32_t)(br * 80 + bseg * 32);

    // ---- ldmatrix lane addressing (byte offsets within a buffer)
    const uint32_t aoff = (uint32_t)(((wm * 32 + (lane & 15)) * SA + ((lane >> 4) * 8)) * 2);
    const uint32_t boff = (uint32_t)(((wn * 64 + (lane & 7) + ((lane >> 4) * 8)) * SA
                                      + (((lane >> 3) & 1) * 8)) * 2);

    float acc[2][8][4];
    #pragma unroll
    for (int mt = 0; mt < 2; ++mt)
        #pragma unroll
        for (int j = 0; j < 8; ++j)
            #pragma unroll
            for (int q = 0; q < 4; ++q) acc[mt][j][q] = 0.f;

    constexpr int NC = CIN / 32;

    // ---- prologue: B chunk 0 via cp.async, A chunk 0 into regs
    {
        CP_ASYNC_16(dstB + OFF_BH, srcBh);
        CP_ASYNC_16(dstB + OFF_BH + 16, srcBh + 8);
        CP_ASYNC_16(dstB + OFF_BL, srcBl);
        CP_ASYNC_16(dstB + OFF_BL + 16, srcBl + 8);
        CP_ASYNC_COMMIT();
    }
    float4 a[4];
    #pragma unroll
    for (int i = 0; i < 4; ++i)
        a[i] = (gA >= 0) ? reinterpret_cast<const float4*>(feats + gA + aseg * 16)[i]
                         : make_float4(0.f, 0.f, 0.f, 0.f);

    for (int c = 0; c < NC; ++c) {
        const uint32_t bufo = (uint32_t)((c & 1) * BUF_SZ);

        // ---- store A regs (split hi/lo) into buffer c&1
        {
            uint4 hv0, lv0, hv1, lv1;
            split2(a[0].x, a[0].y, hv0.x, lv0.x);
            split2(a[0].z, a[0].w, hv0.y, lv0.y);
            split2(a[1].x, a[1].y, hv0.z, lv0.z);
            split2(a[1].z, a[1].w, hv0.w, lv0.w);
            split2(a[2].x, a[2].y, hv1.x, lv1.x);
            split2(a[2].z, a[2].w, hv1.y, lv1.y);
            split2(a[3].x, a[3].y, hv1.z, lv1.z);
            split2(a[3].z, a[3].w, hv1.w, lv1.w);
            char* Ah = smc + bufo + OFF_AH + ar * 80 + aseg * 32;
            char* Al = smc + bufo + OFF_AL + ar * 80 + aseg * 32;
            *reinterpret_cast<uint4*>(Ah)      = hv0;
            *reinterpret_cast<uint4*>(Ah + 16) = hv1;
            *reinterpret_cast<uint4*>(Al)      = lv0;
            *reinterpret_cast<uint4*>(Al + 16) = lv1;
        }
        CP_ASYNC_WAIT0();
        __syncthreads();

        // ---- prefetch chunk c+1 (B via cp.async to other buffer, A to regs)
        if (c + 1 < NC) {
            const int k1 = (c + 1) * 32;
            const uint32_t nb = dstB + (bufo ^ BUF_SZ);
            CP_ASYNC_16(nb + OFF_BH, srcBh + k1);
            CP_ASYNC_16(nb + OFF_BH + 16, srcBh + k1 + 8);
            CP_ASYNC_16(nb + OFF_BL, srcBl + k1);
            CP_ASYNC_16(nb + OFF_BL + 16, srcBl + k1 + 8);
            CP_ASYNC_COMMIT();
            #pragma unroll
            for (int i = 0; i < 4; ++i)
                a[i] = (gA >= 0)
                     ? reinterpret_cast<const float4*>(feats + gA + k1 + aseg * 16)[i]
                     : make_float4(0.f, 0.f, 0.f, 0.f);
        }

        // ---- compute buffer c&1: 2 k16 steps
        #pragma unroll
        for (int ks = 0; ks < 2; ++ks) {
            const uint32_t ka = (uint32_t)(ks * 32);
            uint32_t ah0[4], ah1[4], al0[4], al1[4];
            {
                uint32_t p = sb + bufo + OFF_AH + aoff + ka;
                LDSM_X4(ah0[0], ah0[1], ah0[2], ah0[3], p);
                LDSM_X4(ah1[0], ah1[1], ah1[2], ah1[3], p + 1280);
                uint32_t q = sb + bufo + OFF_AL + aoff + ka;
                LDSM_X4(al0[0], al0[1], al0[2], al0[3], q);
                LDSM_X4(al1[0], al1[1], al1[2], al1[3], q + 1280);
            }
            #pragma unroll
            for (int g = 0; g < 4; ++g) {
                uint32_t bh[4], bl[4];
                uint32_t p = sb + bufo + OFF_BH + boff + ka + (uint32_t)(g * 1280);
                LDSM_X4(bh[0], bh[1], bh[2], bh[3], p);
                LDSM_X4(bl[0], bl[1], bl[2], bl[3], p + (OFF_BL - OFF_BH));
                // frag j=2g : {bh[0],bh[1]} ; j=2g+1 : {bh[2],bh[3]}
                MMA_BF16(acc[0][2 * g],     ah0, bh);
                MMA_BF16(acc[1][2 * g],     ah1, bh);
                MMA_BF16(acc[0][2 * g + 1], ah0, bh + 2);
                MMA_BF16(acc[1][2 * g + 1], ah1, bh + 2);
                MMA_BF16(acc[0][2 * g],     ah0, bl);
                MMA_BF16(acc[1][2 * g],     ah1, bl);
                MMA_BF16(acc[0][2 * g + 1], ah0, bl + 2);
                MMA_BF16(acc[1][2 * g + 1], ah1, bl + 2);
                MMA_BF16(acc[0][2 * g],     al0, bh);
                MMA_BF16(acc[1][2 * g],     al1, bh);
                MMA_BF16(acc[0][2 * g + 1], al0, bh + 2);
                MMA_BF16(acc[1][2 * g + 1], al1, bh + 2);
            }
        }
        __syncthreads();
    }

    // ---- epilogue: scatter-add via vector reductions
    const int ncol = n0 + wn * 64 + 2 * (lane & 3);
    #pragma unroll
    for (int mt = 0; mt < 2; ++mt) {
        int r0 = m0 + wm * 32 + mt * 16 + (lane >> 2);
        int r1 = r0 + 8;
        if (r0 < M) {
            int o = out_map[zM + r0];
            float* p = outb + (size_t)o * OUT_STRIDE + ncol;
            #pragma unroll
            for (int j = 0; j < 8; ++j)
                red_add_v2(p + j * 8, acc[mt][j][0], acc[mt][j][1]);
        }
        if (r1 < M) {
            int o = out_map[zM + r1];
            float* p = outb + (size_t)o * OUT_STRIDE + ncol;
            #pragma unroll
            for (int j = 0; j < 8; ++j)
                red_add_v2(p + j * 8, acc[mt][j][2], acc[mt][j][3]);
        }
    }
}

// ===========================================================================
// BN (eval) + ReLU in place
// ===========================================================================
template <int STRIDE, bool ON_GX>
__global__ void bn_relu_kernel(float* __restrict__ buf,
                               const float* __restrict__ gamma,
                               const float* __restrict__ beta,
                               const float* __restrict__ mean,
                               const float* __restrict__ var) {
    int c = threadIdx.x;
    float s  = gamma[c] * rsqrtf(var[c] + BN_EPS);
    float sh = beta[c] - mean[c] * s;
    float* base = ON_GX ? (float*)g_x : buf;
    for (int row = blockIdx.x; row < NB; row += gridDim.x) {
        size_t idx = (size_t)row * STRIDE + c;
        base[idx] = fmaxf(fmaf(base[idx], s, sh), 0.f);
    }
}

// ===========================================================================
extern "C" void kernel_launch(void* const* d_in, const int* in_sizes, int n_in,
                              void* d_out, int out_size) {
    const float* feats_a    = (const float*)d_in[0];
    const float* feats_b    = (const float*)d_in[1];
    const float* W_t        = (const float*)d_in[2];
    const float* bn_t_gamma = (const float*)d_in[3];
    const float* bn_t_beta  = (const float*)d_in[4];
    const float* bn_t_mean  = (const float*)d_in[5];
    const float* bn_t_var   = (const float*)d_in[6];
    const float* W_c        = (const float*)d_in[7];
    const float* bn_c_gamma = (const float*)d_in[8];
    const float* bn_c_beta  = (const float*)d_in[9];
    const float* bn_c_mean  = (const float*)d_in[10];
    const float* bn_c_var   = (const float*)d_in[11];
    const int*   in_map_t   = (const int*)d_in[12];
    const int*   out_map_t  = (const int*)d_in[13];
    const int*   in_map_c   = (const int*)d_in[14];
    const int*   out_map_c  = (const int*)d_in[15];
    float* out = (float*)d_out;

    cudaFuncSetAttribute(spconv_mma_kernel<CA, CX, false, true>,
                         cudaFuncAttributeMaxDynamicSharedMemorySize, SMEM_TOTAL);
    cudaFuncSetAttribute(spconv_mma_kernel<CX, CO, true, false>,
                         cudaFuncAttributeMaxDynamicSharedMemorySize, SMEM_TOTAL);

    void *wt_hi, *wt_lo, *wc_hi, *wc_lo;
    cudaGetSymbolAddress(&wt_hi, g_Wt_hi);
    cudaGetSymbolAddress(&wt_lo, g_Wt_lo);
    cudaGetSymbolAddress(&wc_hi, g_Wc_hi);
    cudaGetSymbolAddress(&wc_lo, g_Wc_lo);

    // 0) weight transpose + bf16 split
    prep_w_kernel<CA><<<dim3(CO / 32, CA / 32, KT), dim3(32, 8)>>>(
        W_t, (__nv_bfloat16*)wt_hi, (__nv_bfloat16*)wt_lo);
    prep_w_kernel<CX><<<dim3(CO / 32, CX / 32, KC), dim3(32, 8)>>>(
        W_c, (__nv_bfloat16*)wc_hi, (__nv_bfloat16*)wc_lo);

    // 1) init concat buffer + zero output accumulator
    init_x_kernel<<<NB, 128>>>(feats_b);
    {
        int n4 = (int)((size_t)NB * CO / 4);
        zero_f4_kernel<<<(n4 + 255) / 256, 256>>>(out, n4);
    }

    // 2) transpose conv -> g_x[:, 0:256]
    {
        dim3 grid((MT + 127) / 128, 2, KT);
        spconv_mma_kernel<CA, CX, false, true><<<grid, 256, SMEM_TOTAL>>>(
            feats_a, (const __nv_bfloat16*)wt_hi, (const __nv_bfloat16*)wt_lo,
            in_map_t, out_map_t, nullptr, MT);
    }

    // 3) BN + ReLU on xa
    bn_relu_kernel<CX, true><<<2048, 256>>>(nullptr, bn_t_gamma, bn_t_beta,
                                            bn_t_mean, bn_t_var);

    // 4) 3x3x3 conv: g_x(384) -> out
    {
        dim3 grid((MC + 127) / 128, 2, KC);
        spconv_mma_kernel<CX, CO, true, false><<<grid, 256, SMEM_TOTAL>>>(
            nullptr, (const __nv_bfloat16*)wc_hi, (const __nv_bfloat16*)wc_lo,
            in_map_c, out_map_c, out, MC);
    }

    // 5) BN + ReLU on output
    bn_relu_kernel<CO, false><<<2048, 256>>>(out, bn_c_gamma, bn_c_beta,
                                             bn_c_mean, bn_c_var);
}

// round 7
// speedup vs baseline: 1.8905x; 1.0331x over previous
#include <cuda_runtime.h>
#include <cuda_bf16.h>
#include <cstdint>

// Problem constants
#define NA   50000
#define NB   200000
#define CA   256
#define CB   128
#define CX   384
#define CO   256
#define KT   8
#define MT   100000
#define KC   27
#define MC   120000
#define BN_EPS 1e-5f

// Device-resident buffers
__device__ float g_x[(size_t)NB * CO];                        // conv_t fp32 accumulator
__device__ __nv_bfloat16 g_xs[(size_t)NB * 2 * CX];           // x split: [hi 384 | lo 384]
__device__ __nv_bfloat16 g_as[(size_t)NA * 2 * CA];           // feats_a split: [hi 256 | lo 256]
__device__ __nv_bfloat16 g_Wt_hi[(size_t)KT * CO * CA];       // W_t^T [z][n][k]
__device__ __nv_bfloat16 g_Wt_lo[(size_t)KT * CO * CA];
__device__ __nv_bfloat16 g_Wc_hi[(size_t)KC * CO * CX];       // W_c^T [z][n][k]
__device__ __nv_bfloat16 g_Wc_lo[(size_t)KC * CO * CX];

// ===========================================================================
// PTX helpers (generic PTX only — tcgen05 unavailable at compute_103)
// ===========================================================================
__device__ __forceinline__ uint32_t smem_to_u32(const void* p) {
    uint32_t a;
    asm("{ .reg .u64 t; cvta.to.shared.u64 t, %1; cvt.u32.u64 %0, t; }" : "=r"(a) : "l"(p));
    return a;
}

#define CP_ASYNC_16(dst_u32, src_ptr) \
    asm volatile("cp.async.cg.shared.global [%0], [%1], 16;" \
                 :: "r"(dst_u32), "l"(src_ptr) : "memory")
// zfill: src-size register form; 0 -> fill 16B of zeros
#define CP_ASYNC_16Z(dst_u32, src_ptr, zf) \
    asm volatile("cp.async.cg.shared.global [%0], [%1], 16, %2;" \
                 :: "r"(dst_u32), "l"(src_ptr), "r"(zf) : "memory")
#define CP_ASYNC_COMMIT() asm volatile("cp.async.commit_group;" ::: "memory")
#define CP_ASYNC_WAIT1()  asm volatile("cp.async.wait_group 1;" ::: "memory")

#define LDSM_X4(r0, r1, r2, r3, addr) \
    asm volatile("ldmatrix.sync.aligned.m8n8.x4.shared.b16 {%0,%1,%2,%3}, [%4];" \
                 : "=r"(r0), "=r"(r1), "=r"(r2), "=r"(r3) : "r"(addr))

#define MMA_BF16(d, a, b) \
    asm volatile("mma.sync.aligned.m16n8k16.row.col.f32.bf16.bf16.f32 " \
                 "{%0,%1,%2,%3}, {%4,%5,%6,%7}, {%8,%9}, {%0,%1,%2,%3};" \
                 : "+f"((d)[0]), "+f"((d)[1]), "+f"((d)[2]), "+f"((d)[3]) \
                 : "r"((a)[0]), "r"((a)[1]), "r"((a)[2]), "r"((a)[3]), \
                   "r"((b)[0]), "r"((b)[1]))

__device__ __forceinline__ void red_add_v4(float* p, float a, float b, float c, float d) {
    asm volatile("red.global.add.v4.f32 [%0], {%1, %2, %3, %4};"
                 :: "l"(p), "f"(a), "f"(b), "f"(c), "f"(d) : "memory");
}

// Split fp32 pair into packed bf16 hi / lo
__device__ __forceinline__ void split2(float x, float y, uint32_t& h, uint32_t& l) {
    __nv_bfloat162 hh = __float22bfloat162_rn(make_float2(x, y));
    float2 hf = __bfloat1622float2(hh);
    __nv_bfloat162 ll = __float22bfloat162_rn(make_float2(x - hf.x, y - hf.y));
    h = *reinterpret_cast<uint32_t*>(&hh);
    l = *reinterpret_cast<uint32_t*>(&ll);
}

// ===========================================================================
// Prep: transpose W [K][CIN][CO] -> [K][CO][CIN] + bf16 hi/lo split
// ===========================================================================
template <int CIN>
__global__ void prep_w_kernel(const float* __restrict__ W,
                              __nv_bfloat16* __restrict__ hi,
                              __nv_bfloat16* __restrict__ lo) {
    __shared__ float t[32][33];
    const int z = blockIdx.z;
    const int k0 = blockIdx.y * 32, n0 = blockIdx.x * 32;
    const int tx = threadIdx.x, ty = threadIdx.y;   // (32, 8)
    #pragma unroll
    for (int i = 0; i < 4; ++i) {
        int k = k0 + ty + i * 8;
        t[ty + i * 8][tx] = W[((size_t)z * CIN + k) * CO + n0 + tx];
    }
    __syncthreads();
    #pragma unroll
    for (int i = 0; i < 4; ++i) {
        int n = n0 + ty + i * 8;
        float v = t[tx][ty + i * 8];
        __nv_bfloat16 h = __float2bfloat16(v);
        float r = v - __bfloat162float(h);
        size_t o = ((size_t)z * CO + n) * CIN + k0 + tx;
        hi[o] = h;
        lo[o] = __float2bfloat16(r);
    }
}

// ===========================================================================
// Prep: split feats_a rows into g_as = [hi 256 | lo 256] bf16
// ===========================================================================
__global__ void prep_a_kernel(const float* __restrict__ feats_a) {
    int row = blockIdx.x;
    int t = threadIdx.x;          // 64 threads, 4 floats each
    float4 v = reinterpret_cast<const float4*>(feats_a + (size_t)row * CA)[t];
    uint32_t h0, l0, h1, l1;
    split2(v.x, v.y, h0, l0);
    split2(v.z, v.w, h1, l1);
    __nv_bfloat16* xs = g_as + (size_t)row * 2 * CA;
    *reinterpret_cast<uint2*>(xs + 4 * t)      = make_uint2(h0, h1);
    *reinterpret_cast<uint2*>(xs + CA + 4 * t) = make_uint2(l0, l1);
}

// ===========================================================================
// BN+ReLU on conv_t accumulator + concat feats_b + bf16 split -> g_xs
// row layout of g_xs: [hi 384 | lo 384]
// ===========================================================================
__global__ void bn_split_x_kernel(const float* __restrict__ feats_b,
                                  const float* __restrict__ gamma,
                                  const float* __restrict__ beta,
                                  const float* __restrict__ mean,
                                  const float* __restrict__ var) {
    int row = blockIdx.x;
    int t = threadIdx.x;          // 96 active
    if (t >= CX / 4) return;
    float4 v;
    if (t < CA / 4) {
        v = reinterpret_cast<const float4*>(g_x + (size_t)row * CO)[t];
        float4 gm = reinterpret_cast<const float4*>(gamma)[t];
        float4 bt = reinterpret_cast<const float4*>(beta)[t];
        float4 mn = reinterpret_cast<const float4*>(mean)[t];
        float4 vr = reinterpret_cast<const float4*>(var)[t];
        float s0 = gm.x * rsqrtf(vr.x + BN_EPS);
        float s1 = gm.y * rsqrtf(vr.y + BN_EPS);
        float s2 = gm.z * rsqrtf(vr.z + BN_EPS);
        float s3 = gm.w * rsqrtf(vr.w + BN_EPS);
        v.x = fmaxf(fmaf(v.x - mn.x, s0, bt.x), 0.f);
        v.y = fmaxf(fmaf(v.y - mn.y, s1, bt.y), 0.f);
        v.z = fmaxf(fmaf(v.z - mn.z, s2, bt.z), 0.f);
        v.w = fmaxf(fmaf(v.w - mn.w, s3, bt.w), 0.f);
    } else {
        v = reinterpret_cast<const float4*>(feats_b + (size_t)row * CB)[t - CA / 4];
    }
    uint32_t h0, l0, h1, l1;
    split2(v.x, v.y, h0, l0);
    split2(v.z, v.w, h1, l1);
    __nv_bfloat16* xs = g_xs + (size_t)row * 2 * CX;
    *reinterpret_cast<uint2*>(xs + 4 * t)      = make_uint2(h0, h1);
    *reinterpret_cast<uint2*>(xs + CX + 4 * t) = make_uint2(l0, l1);
}

__global__ void zero_f4_kernel(float* __restrict__ p, int n4) {
    int i = blockIdx.x * blockDim.x + threadIdx.x;
    if (i < n4) reinterpret_cast<float4*>(p)[i] = make_float4(0.f, 0.f, 0.f, 0.f);
}

// ===========================================================================
// Sparse conv: cp.async gather (pre-split bf16) -> mma.sync -> coalesced red.v4
// CTA tile: 128 pairs x 256 out-ch (full CO). 8 warps (4M x 2N), warp 32x128.
// K chunks of 32, 3-stage cp.async pipeline.
// Buffer: Ah 10240 | Al 10240 | Bh 20480 | Bl 20480 = 61440 B; 3 stages.
// ===========================================================================
#define OFF_AH    0
#define OFF_AL    10240
#define OFF_BH    20480
#define OFF_BL    40960
#define BUF_SZ    61440
#define NSTAGES   3
#define SMEM_TOTAL (NSTAGES * BUF_SZ)

template <int CIN, bool DST_GX>
__global__ void __launch_bounds__(256, 1)
spconv_mma_kernel(const __nv_bfloat16* __restrict__ xs,   // rows: [hi CIN | lo CIN]
                  const __nv_bfloat16* __restrict__ Whi,
                  const __nv_bfloat16* __restrict__ Wlo,
                  const int* __restrict__ in_map,
                  const int* __restrict__ out_map,
                  float* __restrict__ out_param,
                  int M) {
    extern __shared__ char smc[];
    const uint32_t sb = smem_to_u32(smc);
    float* outb = DST_GX ? (float*)g_x : out_param;

    const int tid  = threadIdx.x;
    const int lane = tid & 31;
    const int w    = tid >> 5;
    const int wm   = w & 3;
    const int wn   = w >> 2;

    const int z  = blockIdx.z;
    const int m0 = blockIdx.x * 128;
    const size_t zM = (size_t)z * M;

    // ---- A gather assignment: thread -> (row=tid>>1, 32B half s=tid&1)
    const int ar = tid >> 1;
    const int as = tid & 1;
    const char* rowp = (const char*)xs;     // dummy for invalid
    uint32_t zf = 0;
    if (m0 + ar < M) {
        rowp = (const char*)(xs + (size_t)in_map[zM + m0 + ar] * (2 * CIN));
        zf = 16;
    }
    const uint32_t dstA = sb + (uint32_t)(ar * 80 + as * 32);

    // ---- B assignment: thread -> one n-row (0..255)
    const __nv_bfloat16* hb = Whi + ((size_t)z * CO + tid) * CIN;
    const __nv_bfloat16* lb = Wlo + ((size_t)z * CO + tid) * CIN;
    const uint32_t dstB = sb + OFF_BH + (uint32_t)(tid * 80);

    // ---- ldmatrix lane addressing (bytes within a stage)
    const uint32_t aoff = (uint32_t)(((wm * 32 + (lane & 15)) * 40 + ((lane >> 4) * 8)) * 2);
    const uint32_t boff = (uint32_t)(((wn * 128 + (lane & 7) + ((lane >> 4) * 8)) * 40
                                      + (((lane >> 3) & 1) * 8)) * 2);

    float acc[2][16][4];
    #pragma unroll
    for (int mt = 0; mt < 2; ++mt)
        #pragma unroll
        for (int j = 0; j < 16; ++j)
            #pragma unroll
            for (int q = 0; q < 4; ++q) acc[mt][j][q] = 0.f;

    constexpr int NC = CIN / 32;
    constexpr int CINB = CIN * 2;   // row hi-span bytes

    // chunk loader
    auto load_chunk = [&](int c) {
        const uint32_t bo = (uint32_t)((c % NSTAGES) * BUF_SZ);
        const int kb = c * 64;      // byte offset of k0 within hi span
        const char* hs = rowp + kb + as * 32;
        const char* ls = rowp + CINB + kb + as * 32;
        CP_ASYNC_16Z(dstA + bo + OFF_AH,      hs,      zf);
        CP_ASYNC_16Z(dstA + bo + OFF_AH + 16, hs + 16, zf);
        CP_ASYNC_16Z(dstA + bo + OFF_AL,      ls,      zf);
        CP_ASYNC_16Z(dstA + bo + OFF_AL + 16, ls + 16, zf);
        const __nv_bfloat16* hk = hb + c * 32;
        const __nv_bfloat16* lk = lb + c * 32;
        #pragma unroll
        for (int q = 0; q < 4; ++q) {
            CP_ASYNC_16(dstB + bo + q * 16,                       hk + q * 8);
            CP_ASYNC_16(dstB + bo + (OFF_BL - OFF_BH) + q * 16,   lk + q * 8);
        }
    };

    // prologue
    load_chunk(0); CP_ASYNC_COMMIT();
    load_chunk(1); CP_ASYNC_COMMIT();

    for (int c = 0; c < NC; ++c) {
        CP_ASYNC_WAIT1();
        __syncthreads();
        if (c + 2 < NC) load_chunk(c + 2);
        CP_ASYNC_COMMIT();

        const uint32_t bo = (uint32_t)((c % NSTAGES) * BUF_SZ);
        #pragma unroll
        for (int ks = 0; ks < 2; ++ks) {
            const uint32_t ka = (uint32_t)(ks * 32);
            uint32_t ah0[4], ah1[4], al0[4], al1[4];
            {
                uint32_t pa = sb + bo + OFF_AH + aoff + ka;
                LDSM_X4(ah0[0], ah0[1], ah0[2], ah0[3], pa);
                LDSM_X4(ah1[0], ah1[1], ah1[2], ah1[3], pa + 1280);
                uint32_t ql = sb + bo + OFF_AL + aoff + ka;
                LDSM_X4(al0[0], al0[1], al0[2], al0[3], ql);
                LDSM_X4(al1[0], al1[1], al1[2], al1[3], ql + 1280);
            }
            #pragma unroll
            for (int g = 0; g < 8; ++g) {
                uint32_t bh[4], bl[4];
                uint32_t pb = sb + bo + OFF_BH + boff + ka + (uint32_t)(g * 1280);
                LDSM_X4(bh[0], bh[1], bh[2], bh[3], pb);
                LDSM_X4(bl[0], bl[1], bl[2], bl[3], pb + (OFF_BL - OFF_BH));
                MMA_BF16(acc[0][2 * g],     ah0, bh);
                MMA_BF16(acc[1][2 * g],     ah1, bh);
                MMA_BF16(acc[0][2 * g + 1], ah0, bh + 2);
                MMA_BF16(acc[1][2 * g + 1], ah1, bh + 2);
                MMA_BF16(acc[0][2 * g],     ah0, bl);
                MMA_BF16(acc[1][2 * g],     ah1, bl);
                MMA_BF16(acc[0][2 * g + 1], ah0, bl + 2);
                MMA_BF16(acc[1][2 * g + 1], ah1, bl + 2);
                MMA_BF16(acc[0][2 * g],     al0, bh);
                MMA_BF16(acc[1][2 * g],     al1, bh);
                MMA_BF16(acc[0][2 * g + 1], al0, bh + 2);
                MMA_BF16(acc[1][2 * g + 1], al1, bh + 2);
            }
        }
    }

    // ---- epilogue: per-warp SMEM transpose -> coalesced red.v4
    __syncthreads();   // staging overlays the pipeline buffers
    float* ws = reinterpret_cast<float*>(smc) + w * (16 * 132);
    #pragma unroll
    for (int mt = 0; mt < 2; ++mt) {
        #pragma unroll
        for (int j = 0; j < 16; ++j) {
            int colo = j * 8 + 2 * (lane & 3);
            *reinterpret_cast<float2*>(ws + (lane >> 2) * 132 + colo) =
                make_float2(acc[mt][j][0], acc[mt][j][1]);
            *reinterpret_cast<float2*>(ws + ((lane >> 2) + 8) * 132 + colo) =
                make_float2(acc[mt][j][2], acc[mt][j][3]);
        }
        __syncwarp();
        #pragma unroll
        for (int i = 0; i < 16; ++i) {
            int mrow = m0 + wm * 32 + mt * 16 + i;
            if (mrow < M) {
                int o = out_map[zM + mrow];
                float* p = outb + (size_t)o * CO + wn * 128 + lane * 4;
                float4 v = *reinterpret_cast<float4*>(ws + i * 132 + lane * 4);
                red_add_v4(p, v.x, v.y, v.z, v.w);
            }
        }
        __syncwarp();
    }
}

// ===========================================================================
// BN (eval) + ReLU on output
// ===========================================================================
__global__ void bn_relu_kernel(float* __restrict__ buf,
                               const float* __restrict__ gamma,
                               const float* __restrict__ beta,
                               const float* __restrict__ mean,
                               const float* __restrict__ var) {
    int c = threadIdx.x;
    float s  = gamma[c] * rsqrtf(var[c] + BN_EPS);
    float sh = beta[c] - mean[c] * s;
    for (int row = blockIdx.x; row < NB; row += gridDim.x) {
        size_t idx = (size_t)row * CO + c;
        buf[idx] = fmaxf(fmaf(buf[idx], s, sh), 0.f);
    }
}

// ===========================================================================
extern "C" void kernel_launch(void* const* d_in, const int* in_sizes, int n_in,
                              void* d_out, int out_size) {
    const float* feats_a    = (const float*)d_in[0];
    const float* feats_b    = (const float*)d_in[1];
    const float* W_t        = (const float*)d_in[2];
    const float* bn_t_gamma = (const float*)d_in[3];
    const float* bn_t_beta  = (const float*)d_in[4];
    const float* bn_t_mean  = (const float*)d_in[5];
    const float* bn_t_var   = (const float*)d_in[6];
    const float* W_c        = (const float*)d_in[7];
    const float* bn_c_gamma = (const float*)d_in[8];
    const float* bn_c_beta  = (const float*)d_in[9];
    const float* bn_c_mean  = (const float*)d_in[10];
    const float* bn_c_var   = (const float*)d_in[11];
    const int*   in_map_t   = (const int*)d_in[12];
    const int*   out_map_t  = (const int*)d_in[13];
    const int*   in_map_c   = (const int*)d_in[14];
    const int*   out_map_c  = (const int*)d_in[15];
    float* out = (float*)d_out;

    cudaFuncSetAttribute(spconv_mma_kernel<CA, true>,
                         cudaFuncAttributeMaxDynamicSharedMemorySize, SMEM_TOTAL);
    cudaFuncSetAttribute(spconv_mma_kernel<CX, false>,
                         cudaFuncAttributeMaxDynamicSharedMemorySize, SMEM_TOTAL);

    void *wt_hi, *wt_lo, *wc_hi, *wc_lo, *gx, *gas, *gxs;
    cudaGetSymbolAddress(&wt_hi, g_Wt_hi);
    cudaGetSymbolAddress(&wt_lo, g_Wt_lo);
    cudaGetSymbolAddress(&wc_hi, g_Wc_hi);
    cudaGetSymbolAddress(&wc_lo, g_Wc_lo);
    cudaGetSymbolAddress(&gx, g_x);
    cudaGetSymbolAddress(&gas, g_as);
    cudaGetSymbolAddress(&gxs, g_xs);

    // 0) weight transpose + split ; feats_a split ; zero accumulators
    prep_w_kernel<CA><<<dim3(CO / 32, CA / 32, KT), dim3(32, 8)>>>(
        W_t, (__nv_bfloat16*)wt_hi, (__nv_bfloat16*)wt_lo);
    prep_w_kernel<CX><<<dim3(CO / 32, CX / 32, KC), dim3(32, 8)>>>(
        W_c, (__nv_bfloat16*)wc_hi, (__nv_bfloat16*)wc_lo);
    prep_a_kernel<<<NA, 64>>>(feats_a);
    {
        int n4 = (int)((size_t)NB * CO / 4);
        zero_f4_kernel<<<(n4 + 255) / 256, 256>>>((float*)gx, n4);
        zero_f4_kernel<<<(n4 + 255) / 256, 256>>>(out, n4);
    }

    // 1) transpose conv: g_as -> g_x (fp32 accum)
    {
        dim3 grid((MT + 127) / 128, 1, KT);
        spconv_mma_kernel<CA, true><<<grid, 256, SMEM_TOTAL>>>(
            (const __nv_bfloat16*)gas,
            (const __nv_bfloat16*)wt_hi, (const __nv_bfloat16*)wt_lo,
            in_map_t, out_map_t, nullptr, MT);
    }

    // 2) BN+ReLU + concat + split -> g_xs
    bn_split_x_kernel<<<NB, 128>>>(feats_b, bn_t_gamma, bn_t_beta,
                                   bn_t_mean, bn_t_var);

    // 3) 3x3x3 conv: g_xs -> out
    {
        dim3 grid((MC + 127) / 128, 1, KC);
        spconv_mma_kernel<CX, false><<<grid, 256, SMEM_TOTAL>>>(
            (const __nv_bfloat16*)gxs,
            (const __nv_bfloat16*)wc_hi, (const __nv_bfloat16*)wc_lo,
            in_map_c, out_map_c, out, MC);
    }

    // 4) BN + ReLU on output
    bn_relu_kernel<<<2048, 256>>>(out, bn_c_gamma, bn_c_beta,
                                  bn_c_mean, bn_c_var);
}

// round 8
// speedup vs baseline: 2.3728x; 1.2552x over previous
#include <cuda_runtime.h>
#include <cuda_fp16.h>
#include <cstdint>

// Problem constants
#define NA   50000
#define NB   200000
#define CA   256
#define CB   128
#define CX   384
#define CO   256
#define KT   8
#define MT   100000
#define KC   27
#define MC   120000
#define BN_EPS 1e-5f

// W is pre-scaled by 2^10 before fp16 split (keeps lo plane normal);
// spconv epilogue multiplies by 2^-10.
#define W_SCALE      1024.0f
#define INV_W_SCALE  0.0009765625f

// Device-resident buffers
__device__ float g_x[(size_t)NB * CO];                 // conv_t fp32 accumulator
__device__ __half g_xs[(size_t)NB * CX];               // x (BN+ReLU | feats_b) fp16
__device__ __half g_as[(size_t)NA * CA];               // feats_a fp16
__device__ __half g_Wt_hi[(size_t)KT * CO * CA];       // W_t^T [z][n][k], x1024, fp16 split
__device__ __half g_Wt_lo[(size_t)KT * CO * CA];
__device__ __half g_Wc_hi[(size_t)KC * CO * CX];       // W_c^T [z][n][k]
__device__ __half g_Wc_lo[(size_t)KC * CO * CX];

// ===========================================================================
// PTX helpers (generic PTX only — tcgen05 unavailable at compute_103)
// ===========================================================================
__device__ __forceinline__ uint32_t smem_to_u32(const void* p) {
    uint32_t a;
    asm("{ .reg .u64 t; cvta.to.shared.u64 t, %1; cvt.u32.u64 %0, t; }" : "=r"(a) : "l"(p));
    return a;
}

#define CP_ASYNC_16(dst_u32, src_ptr) \
    asm volatile("cp.async.cg.shared.global [%0], [%1], 16;" \
                 :: "r"(dst_u32), "l"(src_ptr) : "memory")
#define CP_ASYNC_16Z(dst_u32, src_ptr, zf) \
    asm volatile("cp.async.cg.shared.global [%0], [%1], 16, %2;" \
                 :: "r"(dst_u32), "l"(src_ptr), "r"(zf) : "memory")
#define CP_ASYNC_COMMIT() asm volatile("cp.async.commit_group;" ::: "memory")
#define CP_ASYNC_WAIT1()  asm volatile("cp.async.wait_group 1;" ::: "memory")

#define LDSM_X4(r0, r1, r2, r3, addr) \
    asm volatile("ldmatrix.sync.aligned.m8n8.x4.shared.b16 {%0,%1,%2,%3}, [%4];" \
                 : "=r"(r0), "=r"(r1), "=r"(r2), "=r"(r3) : "r"(addr))

#define MMA_F16(d, a, b) \
    asm volatile("mma.sync.aligned.m16n8k16.row.col.f32.f16.f16.f32 " \
                 "{%0,%1,%2,%3}, {%4,%5,%6,%7}, {%8,%9}, {%0,%1,%2,%3};" \
                 : "+f"((d)[0]), "+f"((d)[1]), "+f"((d)[2]), "+f"((d)[3]) \
                 : "r"((a)[0]), "r"((a)[1]), "r"((a)[2]), "r"((a)[3]), \
                   "r"((b)[0]), "r"((b)[1]))

__device__ __forceinline__ void red_add_v4(float* p, float a, float b, float c, float d) {
    asm volatile("red.global.add.v4.f32 [%0], {%1, %2, %3, %4};"
                 :: "l"(p), "f"(a), "f"(b), "f"(c), "f"(d) : "memory");
}

// ===========================================================================
// Prep: transpose W [K][CIN][CO] -> [K][CO][CIN], scale by 1024, fp16 hi/lo
// ===========================================================================
template <int CIN>
__global__ void prep_w_kernel(const float* __restrict__ W,
                              __half* __restrict__ hi,
                              __half* __restrict__ lo) {
    __shared__ float t[32][33];
    const int z = blockIdx.z;
    const int k0 = blockIdx.y * 32, n0 = blockIdx.x * 32;
    const int tx = threadIdx.x, ty = threadIdx.y;   // (32, 8)
    #pragma unroll
    for (int i = 0; i < 4; ++i) {
        int k = k0 + ty + i * 8;
        t[ty + i * 8][tx] = W[((size_t)z * CIN + k) * CO + n0 + tx];
    }
    __syncthreads();
    #pragma unroll
    for (int i = 0; i < 4; ++i) {
        int n = n0 + ty + i * 8;
        float v = t[tx][ty + i * 8] * W_SCALE;
        __half h = __float2half_rn(v);
        float r = v - __half2float(h);
        size_t o = ((size_t)z * CO + n) * CIN + k0 + tx;
        hi[o] = h;
        lo[o] = __float2half_rn(r);
    }
}

// ===========================================================================
// Prep: feats_a -> fp16
// ===========================================================================
__global__ void prep_a_kernel(const float* __restrict__ feats_a) {
    int row = blockIdx.x;
    int t = threadIdx.x;          // 64 threads, 4 floats each
    float4 v = reinterpret_cast<const float4*>(feats_a + (size_t)row * CA)[t];
    __half2 h0 = __floats2half2_rn(v.x, v.y);
    __half2 h1 = __floats2half2_rn(v.z, v.w);
    *reinterpret_cast<__half2*>(g_as + (size_t)row * CA + 4 * t)     = h0;
    *reinterpret_cast<__half2*>(g_as + (size_t)row * CA + 4 * t + 2) = h1;
}

// ===========================================================================
// BN+ReLU on conv_t accumulator + concat feats_b -> fp16 g_xs
// ===========================================================================
__global__ void bn_split_x_kernel(const float* __restrict__ feats_b,
                                  const float* __restrict__ gamma,
                                  const float* __restrict__ beta,
                                  const float* __restrict__ mean,
                                  const float* __restrict__ var) {
    int row = blockIdx.x;
    int t = threadIdx.x;          // 96 active
    if (t >= CX / 4) return;
    float4 v;
    if (t < CA / 4) {
        v = reinterpret_cast<const float4*>(g_x + (size_t)row * CO)[t];
        float4 gm = reinterpret_cast<const float4*>(gamma)[t];
        float4 bt = reinterpret_cast<const float4*>(beta)[t];
        float4 mn = reinterpret_cast<const float4*>(mean)[t];
        float4 vr = reinterpret_cast<const float4*>(var)[t];
        v.x = fmaxf(fmaf(v.x - mn.x, gm.x * rsqrtf(vr.x + BN_EPS), bt.x), 0.f);
        v.y = fmaxf(fmaf(v.y - mn.y, gm.y * rsqrtf(vr.y + BN_EPS), bt.y), 0.f);
        v.z = fmaxf(fmaf(v.z - mn.z, gm.z * rsqrtf(vr.z + BN_EPS), bt.z), 0.f);
        v.w = fmaxf(fmaf(v.w - mn.w, gm.w * rsqrtf(vr.w + BN_EPS), bt.w), 0.f);
    } else {
        v = reinterpret_cast<const float4*>(feats_b + (size_t)row * CB)[t - CA / 4];
    }
    __half2 h0 = __floats2half2_rn(v.x, v.y);
    __half2 h1 = __floats2half2_rn(v.z, v.w);
    __half* xs = g_xs + (size_t)row * CX + 4 * t;
    *reinterpret_cast<__half2*>(xs)     = h0;
    *reinterpret_cast<__half2*>(xs + 2) = h1;
}

__global__ void zero_f4_kernel(float* __restrict__ p, int n4) {
    int i = blockIdx.x * blockDim.x + threadIdx.x;
    if (i < n4) reinterpret_cast<float4*>(p)[i] = make_float4(0.f, 0.f, 0.f, 0.f);
}

// ===========================================================================
// Sparse conv (fp16 2-term): A fp16 (one plane) x (Whi + Wlo) -> fp32 acc
// CTA tile: 128 pairs x 256 out-ch. 8 warps (2M x 4N), warp tile 64x64.
// K chunks of 32, 3-stage cp.async pipeline.
// Stage: Ah 10240 | Bh 20480 | Bl 20480 = 51200 B; 3 stages = 153600 B.
// ===========================================================================
#define OFF_AH    0
#define OFF_BH    10240
#define OFF_BL    30720
#define BUF_SZ    51200
#define NSTAGES   3
#define SMEM_TOTAL (NSTAGES * BUF_SZ)

template <int CIN, bool DST_GX>
__global__ void __launch_bounds__(256, 1)
spconv_mma_kernel(const __half* __restrict__ xs,
                  const __half* __restrict__ Whi,
                  const __half* __restrict__ Wlo,
                  const int* __restrict__ in_map,
                  const int* __restrict__ out_map,
                  float* __restrict__ out_param,
                  int M) {
    extern __shared__ char smc[];
    const uint32_t sb = smem_to_u32(smc);
    float* outb = DST_GX ? (float*)g_x : out_param;

    const int tid  = threadIdx.x;
    const int lane = tid & 31;
    const int w    = tid >> 5;
    const int wm   = w & 1;          // 2 M-groups of 64 rows
    const int wn   = w >> 1;         // 4 N-groups of 64 cols

    const int z  = blockIdx.z;
    const int m0 = blockIdx.x * 128;
    const size_t zM = (size_t)z * M;

    // ---- A gather: thread -> (row = tid>>1, 32B half = tid&1)
    const int ar = tid >> 1;
    const int as = tid & 1;
    const char* rowp = (const char*)xs;
    uint32_t zf = 0;
    if (m0 + ar < M) {
        rowp = (const char*)(xs + (size_t)in_map[zM + m0 + ar] * CIN);
        zf = 16;
    }
    const uint32_t dstA = sb + OFF_AH + (uint32_t)(ar * 80 + as * 32);

    // ---- B: thread -> one n-row (0..255), 64B hi + 64B lo per chunk
    const __half* hb = Whi + ((size_t)z * CO + tid) * CIN;
    const __half* lb = Wlo + ((size_t)z * CO + tid) * CIN;
    const uint32_t dstB = sb + OFF_BH + (uint32_t)(tid * 80);

    // ---- ldmatrix lane addressing (bytes within a stage)
    const uint32_t aoff = (uint32_t)(((wm * 64 + (lane & 15)) * 40 + ((lane >> 4) * 8)) * 2);
    const uint32_t boff = (uint32_t)(((wn * 64 + (lane & 7) + ((lane >> 4) * 8)) * 40
                                      + (((lane >> 3) & 1) * 8)) * 2);

    float acc[4][8][4];
    #pragma unroll
    for (int i = 0; i < 4; ++i)
        #pragma unroll
        for (int j = 0; j < 8; ++j)
            #pragma unroll
            for (int q = 0; q < 4; ++q) acc[i][j][q] = 0.f;

    constexpr int NC = CIN / 32;

    auto load_chunk = [&](int c) {
        const uint32_t bo = (uint32_t)((c % NSTAGES) * BUF_SZ);
        const char* hs = rowp + c * 64 + as * 32;
        CP_ASYNC_16Z(dstA + bo,      hs,      zf);
        CP_ASYNC_16Z(dstA + bo + 16, hs + 16, zf);
        const __half* hk = hb + c * 32;
        const __half* lk = lb + c * 32;
        #pragma unroll
        for (int q = 0; q < 4; ++q) {
            CP_ASYNC_16(dstB + bo + q * 16,                     hk + q * 8);
            CP_ASYNC_16(dstB + bo + (OFF_BL - OFF_BH) + q * 16, lk + q * 8);
        }
    };

    load_chunk(0); CP_ASYNC_COMMIT();
    load_chunk(1); CP_ASYNC_COMMIT();

    for (int c = 0; c < NC; ++c) {
        CP_ASYNC_WAIT1();
        __syncthreads();
        if (c + 2 < NC) load_chunk(c + 2);
        CP_ASYNC_COMMIT();

        const uint32_t bo = (uint32_t)((c % NSTAGES) * BUF_SZ);
        #pragma unroll
        for (int ks = 0; ks < 2; ++ks) {
            const uint32_t ka = (uint32_t)(ks * 32);
            uint32_t ah[4][4];
            #pragma unroll
            for (int i = 0; i < 4; ++i) {
                uint32_t pa = sb + bo + OFF_AH + aoff + ka + (uint32_t)(i * 1280);
                LDSM_X4(ah[i][0], ah[i][1], ah[i][2], ah[i][3], pa);
            }
            #pragma unroll
            for (int g = 0; g < 4; ++g) {
                uint32_t bh[4], bl[4];
                uint32_t pb = sb + bo + OFF_BH + boff + ka + (uint32_t)(g * 1280);
                LDSM_X4(bh[0], bh[1], bh[2], bh[3], pb);
                LDSM_X4(bl[0], bl[1], bl[2], bl[3], pb + (OFF_BL - OFF_BH));
                #pragma unroll
                for (int i = 0; i < 4; ++i) {
                    MMA_F16(acc[i][2 * g],     ah[i], bh);
                    MMA_F16(acc[i][2 * g + 1], ah[i], bh + 2);
                    MMA_F16(acc[i][2 * g],     ah[i], bl);
                    MMA_F16(acc[i][2 * g + 1], ah[i], bl + 2);
                }
            }
        }
    }

    // ---- epilogue: undo W scale, per-warp SMEM transpose, coalesced red.v4
    __syncthreads();   // staging overlays pipeline buffers
    float* ws = reinterpret_cast<float*>(smc) + w * (16 * 68);
    const int ncol = wn * 64 + (lane & 15) * 4;
    #pragma unroll
    for (int i = 0; i < 4; ++i) {
        #pragma unroll
        for (int j = 0; j < 8; ++j) {
            int colo = j * 8 + 2 * (lane & 3);
            *reinterpret_cast<float2*>(ws + (lane >> 2) * 68 + colo) =
                make_float2(acc[i][j][0] * INV_W_SCALE, acc[i][j][1] * INV_W_SCALE);
            *reinterpret_cast<float2*>(ws + ((lane >> 2) + 8) * 68 + colo) =
                make_float2(acc[i][j][2] * INV_W_SCALE, acc[i][j][3] * INV_W_SCALE);
        }
        __syncwarp();
        #pragma unroll
        for (int r = 0; r < 8; ++r) {
            int row = r * 2 + (lane >> 4);
            int mrow = m0 + wm * 64 + i * 16 + row;
            if (mrow < M) {
                int o = out_map[zM + mrow];
                float4 v = *reinterpret_cast<float4*>(ws + row * 68 + (lane & 15) * 4);
                red_add_v4(outb + (size_t)o * CO + ncol, v.x, v.y, v.z, v.w);
            }
        }
        __syncwarp();
    }
}

// ===========================================================================
// BN (eval) + ReLU on output
// ===========================================================================
__global__ void bn_relu_kernel(float* __restrict__ buf,
                               const float* __restrict__ gamma,
                               const float* __restrict__ beta,
                               const float* __restrict__ mean,
                               const float* __restrict__ var) {
    int c = threadIdx.x;
    float s  = gamma[c] * rsqrtf(var[c] + BN_EPS);
    float sh = beta[c] - mean[c] * s;
    for (int row = blockIdx.x; row < NB; row += gridDim.x) {
        size_t idx = (size_t)row * CO + c;
        buf[idx] = fmaxf(fmaf(buf[idx], s, sh), 0.f);
    }
}

// ===========================================================================
extern "C" void kernel_launch(void* const* d_in, const int* in_sizes, int n_in,
                              void* d_out, int out_size) {
    const float* feats_a    = (const float*)d_in[0];
    const float* feats_b    = (const float*)d_in[1];
    const float* W_t        = (const float*)d_in[2];
    const float* bn_t_gamma = (const float*)d_in[3];
    const float* bn_t_beta  = (const float*)d_in[4];
    const float* bn_t_mean  = (const float*)d_in[5];
    const float* bn_t_var   = (const float*)d_in[6];
    const float* W_c        = (const float*)d_in[7];
    const float* bn_c_gamma = (const float*)d_in[8];
    const float* bn_c_beta  = (const float*)d_in[9];
    const float* bn_c_mean  = (const float*)d_in[10];
    const float* bn_c_var   = (const float*)d_in[11];
    const int*   in_map_t   = (const int*)d_in[12];
    const int*   out_map_t  = (const int*)d_in[13];
    const int*   in_map_c   = (const int*)d_in[14];
    const int*   out_map_c  = (const int*)d_in[15];
    float* out = (float*)d_out;

    cudaFuncSetAttribute(spconv_mma_kernel<CA, true>,
                         cudaFuncAttributeMaxDynamicSharedMemorySize, SMEM_TOTAL);
    cudaFuncSetAttribute(spconv_mma_kernel<CX, false>,
                         cudaFuncAttributeMaxDynamicSharedMemorySize, SMEM_TOTAL);

    void *wt_hi, *wt_lo, *wc_hi, *wc_lo, *gx, *gas, *gxs;
    cudaGetSymbolAddress(&wt_hi, g_Wt_hi);
    cudaGetSymbolAddress(&wt_lo, g_Wt_lo);
    cudaGetSymbolAddress(&wc_hi, g_Wc_hi);
    cudaGetSymbolAddress(&wc_lo, g_Wc_lo);
    cudaGetSymbolAddress(&gx, g_x);
    cudaGetSymbolAddress(&gas, g_as);
    cudaGetSymbolAddress(&gxs, g_xs);

    // 0) weight transpose + scale + fp16 split ; feats_a fp16 ; zero accums
    prep_w_kernel<CA><<<dim3(CO / 32, CA / 32, KT), dim3(32, 8)>>>(
        W_t, (__half*)wt_hi, (__half*)wt_lo);
    prep_w_kernel<CX><<<dim3(CO / 32, CX / 32, KC), dim3(32, 8)>>>(
        W_c, (__half*)wc_hi, (__half*)wc_lo);
    prep_a_kernel<<<NA, 64>>>(feats_a);
    {
        int n4 = (int)((size_t)NB * CO / 4);
        zero_f4_kernel<<<(n4 + 255) / 256, 256>>>((float*)gx, n4);
        zero_f4_kernel<<<(n4 + 255) / 256, 256>>>(out, n4);
    }

    // 1) transpose conv: g_as -> g_x (fp32 accum)
    {
        dim3 grid((MT + 127) / 128, 1, KT);
        spconv_mma_kernel<CA, true><<<grid, 256, SMEM_TOTAL>>>(
            (const __half*)gas, (const __half*)wt_hi, (const __half*)wt_lo,
            in_map_t, out_map_t, nullptr, MT);
    }

    // 2) BN+ReLU + concat -> g_xs (fp16)
    bn_split_x_kernel<<<NB, 128>>>(feats_b, bn_t_gamma, bn_t_beta,
                                   bn_t_mean, bn_t_var);

    // 3) 3x3x3 conv: g_xs -> out
    {
        dim3 grid((MC + 127) / 128, 1, KC);
        spconv_mma_kernel<CX, false><<<grid, 256, SMEM_TOTAL>>>(
            (const __half*)gxs, (const __half*)wc_hi, (const __half*)wc_lo,
            in_map_c, out_map_c, out, MC);
    }

    // 4) BN + ReLU on output
    bn_relu_kernel<<<2048, 256>>>(out, bn_c_gamma, bn_c_beta,
                                  bn_c_mean, bn_c_var);
}

// round 9
// speedup vs baseline: 3.8716x; 1.6316x over previous
#include <cuda_runtime.h>
#include <cuda_fp16.h>
#include <cstdint>

// Problem constants
#define NA   50000
#define NB   200000
#define CA   256
#define CB   128
#define CX   384
#define CO   256
#define KT   8
#define MT   100000
#define KC   27
#define MC   120000
#define BN_EPS 1e-5f

// Device-resident buffers
__device__ float g_x[(size_t)NB * CO];                 // conv_t fp32 accumulator
__device__ __half g_xs[(size_t)NB * CX];               // x (BN+ReLU | feats_b) fp16
__device__ __half g_as[(size_t)NA * CA];               // feats_a fp16
__device__ __half g_Wt[(size_t)KT * CO * CA];          // W_t^T [z][n][k] fp16
__device__ __half g_Wc[(size_t)KC * CO * CX];          // W_c^T [z][n][k] fp16

// ===========================================================================
// PTX helpers (generic PTX only — tcgen05 unavailable at compute_103)
// ===========================================================================
__device__ __forceinline__ uint32_t smem_to_u32(const void* p) {
    uint32_t a;
    asm("{ .reg .u64 t; cvta.to.shared.u64 t, %1; cvt.u32.u64 %0, t; }" : "=r"(a) : "l"(p));
    return a;
}

#define CP_ASYNC_16(dst_u32, src_ptr) \
    asm volatile("cp.async.cg.shared.global [%0], [%1], 16;" \
                 :: "r"(dst_u32), "l"(src_ptr) : "memory")
#define CP_ASYNC_16Z(dst_u32, src_ptr, zf) \
    asm volatile("cp.async.cg.shared.global [%0], [%1], 16, %2;" \
                 :: "r"(dst_u32), "l"(src_ptr), "r"(zf) : "memory")
#define CP_ASYNC_COMMIT() asm volatile("cp.async.commit_group;" ::: "memory")
#define CP_ASYNC_WAIT2()  asm volatile("cp.async.wait_group 2;" ::: "memory")

#define LDSM_X4(r0, r1, r2, r3, addr) \
    asm volatile("ldmatrix.sync.aligned.m8n8.x4.shared.b16 {%0,%1,%2,%3}, [%4];" \
                 : "=r"(r0), "=r"(r1), "=r"(r2), "=r"(r3) : "r"(addr))

#define MMA_F16(d, a, b) \
    asm volatile("mma.sync.aligned.m16n8k16.row.col.f32.f16.f16.f32 " \
                 "{%0,%1,%2,%3}, {%4,%5,%6,%7}, {%8,%9}, {%0,%1,%2,%3};" \
                 : "+f"((d)[0]), "+f"((d)[1]), "+f"((d)[2]), "+f"((d)[3]) \
                 : "r"((a)[0]), "r"((a)[1]), "r"((a)[2]), "r"((a)[3]), \
                   "r"((b)[0]), "r"((b)[1]))

__device__ __forceinline__ void red_add_v4(float* p, float a, float b, float c, float d) {
    asm volatile("red.global.add.v4.f32 [%0], {%1, %2, %3, %4};"
                 :: "l"(p), "f"(a), "f"(b), "f"(c), "f"(d) : "memory");
}

// ===========================================================================
// Prep: transpose W [K][CIN][CO] -> [K][CO][CIN], fp16
// ===========================================================================
template <int CIN>
__global__ void prep_w_kernel(const float* __restrict__ W,
                              __half* __restrict__ wh) {
    __shared__ float t[32][33];
    const int z = blockIdx.z;
    const int k0 = blockIdx.y * 32, n0 = blockIdx.x * 32;
    const int tx = threadIdx.x, ty = threadIdx.y;   // (32, 8)
    #pragma unroll
    for (int i = 0; i < 4; ++i) {
        int k = k0 + ty + i * 8;
        t[ty + i * 8][tx] = W[((size_t)z * CIN + k) * CO + n0 + tx];
    }
    __syncthreads();
    #pragma unroll
    for (int i = 0; i < 4; ++i) {
        int n = n0 + ty + i * 8;
        wh[((size_t)z * CO + n) * CIN + k0 + tx] = __float2half_rn(t[tx][ty + i * 8]);
    }
}

// ===========================================================================
// Prep: feats_a -> fp16
// ===========================================================================
__global__ void prep_a_kernel(const float* __restrict__ feats_a) {
    int row = blockIdx.x;
    int t = threadIdx.x;          // 64 threads, 4 floats each
    float4 v = reinterpret_cast<const float4*>(feats_a + (size_t)row * CA)[t];
    __half2 h0 = __floats2half2_rn(v.x, v.y);
    __half2 h1 = __floats2half2_rn(v.z, v.w);
    *reinterpret_cast<__half2*>(g_as + (size_t)row * CA + 4 * t)     = h0;
    *reinterpret_cast<__half2*>(g_as + (size_t)row * CA + 4 * t + 2) = h1;
}

// ===========================================================================
// BN+ReLU on conv_t accumulator + concat feats_b -> fp16 g_xs
// ===========================================================================
__global__ void bn_split_x_kernel(const float* __restrict__ feats_b,
                                  const float* __restrict__ gamma,
                                  const float* __restrict__ beta,
                                  const float* __restrict__ mean,
                                  const float* __restrict__ var) {
    int row = blockIdx.x;
    int t = threadIdx.x;          // 96 active
    if (t >= CX / 4) return;
    float4 v;
    if (t < CA / 4) {
        v = reinterpret_cast<const float4*>(g_x + (size_t)row * CO)[t];
        float4 gm = reinterpret_cast<const float4*>(gamma)[t];
        float4 bt = reinterpret_cast<const float4*>(beta)[t];
        float4 mn = reinterpret_cast<const float4*>(mean)[t];
        float4 vr = reinterpret_cast<const float4*>(var)[t];
        v.x = fmaxf(fmaf(v.x - mn.x, gm.x * rsqrtf(vr.x + BN_EPS), bt.x), 0.f);
        v.y = fmaxf(fmaf(v.y - mn.y, gm.y * rsqrtf(vr.y + BN_EPS), bt.y), 0.f);
        v.z = fmaxf(fmaf(v.z - mn.z, gm.z * rsqrtf(vr.z + BN_EPS), bt.z), 0.f);
        v.w = fmaxf(fmaf(v.w - mn.w, gm.w * rsqrtf(vr.w + BN_EPS), bt.w), 0.f);
    } else {
        v = reinterpret_cast<const float4*>(feats_b + (size_t)row * CB)[t - CA / 4];
    }
    __half2 h0 = __floats2half2_rn(v.x, v.y);
    __half2 h1 = __floats2half2_rn(v.z, v.w);
    __half* xs = g_xs + (size_t)row * CX + 4 * t;
    *reinterpret_cast<__half2*>(xs)     = h0;
    *reinterpret_cast<__half2*>(xs + 2) = h1;
}

__global__ void zero_f4_kernel(float* __restrict__ p, int n4) {
    int i = blockIdx.x * blockDim.x + threadIdx.x;
    if (i < n4) reinterpret_cast<float4*>(p)[i] = make_float4(0.f, 0.f, 0.f, 0.f);
}

// ===========================================================================
// Sparse conv (single fp16 pass): A fp16 x W fp16 -> fp32 acc -> red.v4
// CTA tile: 128 pairs x 256 out-ch. 8 warps (2M x 4N), warp tile 64x64.
// K chunks of 32, 4-stage cp.async pipeline (wait_group 2).
// Stage: A 10240 | B 20480 = 30720 B; 4 stages = 122880 B.
// ===========================================================================
#define OFF_B     10240
#define BUF_SZ    30720
#define NSTAGES   4
#define SMEM_TOTAL (NSTAGES * BUF_SZ)

template <int CIN, bool DST_GX>
__global__ void __launch_bounds__(256, 1)
spconv_mma_kernel(const __half* __restrict__ xs,
                  const __half* __restrict__ Wh,
                  const int* __restrict__ in_map,
                  const int* __restrict__ out_map,
                  float* __restrict__ out_param,
                  int M) {
    extern __shared__ char smc[];
    const uint32_t sb = smem_to_u32(smc);
    float* outb = DST_GX ? (float*)g_x : out_param;

    const int tid  = threadIdx.x;
    const int lane = tid & 31;
    const int w    = tid >> 5;
    const int wm   = w & 1;          // 2 M-groups of 64 rows
    const int wn   = w >> 1;         // 4 N-groups of 64 cols

    const int z  = blockIdx.z;
    const int m0 = blockIdx.x * 128;
    const size_t zM = (size_t)z * M;

    // ---- A gather: thread -> (row = tid>>1, 32B half = tid&1)
    const int ar = tid >> 1;
    const int as = tid & 1;
    const char* rowp = (const char*)xs;
    uint32_t zf = 0;
    if (m0 + ar < M) {
        rowp = (const char*)(xs + (size_t)in_map[zM + m0 + ar] * CIN);
        zf = 16;
    }
    const uint32_t dstA = sb + (uint32_t)(ar * 80 + as * 32);

    // ---- B: thread -> one n-row (0..255), 64B per chunk
    const __half* hb = Wh + ((size_t)z * CO + tid) * CIN;
    const uint32_t dstB = sb + OFF_B + (uint32_t)(tid * 80);

    // ---- ldmatrix lane addressing (bytes within a stage)
    const uint32_t aoff = (uint32_t)(((wm * 64 + (lane & 15)) * 40 + ((lane >> 4) * 8)) * 2);
    const uint32_t boff = (uint32_t)(((wn * 64 + (lane & 7) + ((lane >> 4) * 8)) * 40
                                      + (((lane >> 3) & 1) * 8)) * 2);

    float acc[4][8][4];
    #pragma unroll
    for (int i = 0; i < 4; ++i)
        #pragma unroll
        for (int j = 0; j < 8; ++j)
            #pragma unroll
            for (int q = 0; q < 4; ++q) acc[i][j][q] = 0.f;

    constexpr int NC = CIN / 32;

    auto load_chunk = [&](int c) {
        const uint32_t bo = (uint32_t)((c & (NSTAGES - 1)) * BUF_SZ);
        const char* hs = rowp + c * 64 + as * 32;
        CP_ASYNC_16Z(dstA + bo,      hs,      zf);
        CP_ASYNC_16Z(dstA + bo + 16, hs + 16, zf);
        const __half* hk = hb + c * 32;
        #pragma unroll
        for (int q = 0; q < 4; ++q)
            CP_ASYNC_16(dstB + bo + q * 16, hk + q * 8);
    };

    load_chunk(0); CP_ASYNC_COMMIT();
    load_chunk(1); CP_ASYNC_COMMIT();
    load_chunk(2); CP_ASYNC_COMMIT();

    for (int c = 0; c < NC; ++c) {
        CP_ASYNC_WAIT2();
        __syncthreads();
        if (c + 3 < NC) load_chunk(c + 3);
        CP_ASYNC_COMMIT();

        const uint32_t bo = (uint32_t)((c & (NSTAGES - 1)) * BUF_SZ);
        #pragma unroll
        for (int ks = 0; ks < 2; ++ks) {
            const uint32_t ka = (uint32_t)(ks * 32);
            uint32_t ah[4][4];
            #pragma unroll
            for (int i = 0; i < 4; ++i) {
                uint32_t pa = sb + bo + aoff + ka + (uint32_t)(i * 1280);
                LDSM_X4(ah[i][0], ah[i][1], ah[i][2], ah[i][3], pa);
            }
            #pragma unroll
            for (int g = 0; g < 4; ++g) {
                uint32_t bh[4];
                uint32_t pb = sb + bo + OFF_B + boff + ka + (uint32_t)(g * 1280);
                LDSM_X4(bh[0], bh[1], bh[2], bh[3], pb);
                #pragma unroll
                for (int i = 0; i < 4; ++i) {
                    MMA_F16(acc[i][2 * g],     ah[i], bh);
                    MMA_F16(acc[i][2 * g + 1], ah[i], bh + 2);
                }
            }
        }
    }

    // ---- epilogue: per-warp SMEM transpose, coalesced red.v4
    __syncthreads();   // staging overlays pipeline buffers
    float* ws = reinterpret_cast<float*>(smc) + w * (16 * 68);
    const int ncol = wn * 64 + (lane & 15) * 4;
    #pragma unroll
    for (int i = 0; i < 4; ++i) {
        #pragma unroll
        for (int j = 0; j < 8; ++j) {
            int colo = j * 8 + 2 * (lane & 3);
            *reinterpret_cast<float2*>(ws + (lane >> 2) * 68 + colo) =
                make_float2(acc[i][j][0], acc[i][j][1]);
            *reinterpret_cast<float2*>(ws + ((lane >> 2) + 8) * 68 + colo) =
                make_float2(acc[i][j][2], acc[i][j][3]);
        }
        __syncwarp();
        #pragma unroll
        for (int r = 0; r < 8; ++r) {
            int row = r * 2 + (lane >> 4);
            int mrow = m0 + wm * 64 + i * 16 + row;
            if (mrow < M) {
                int o = out_map[zM + mrow];
                float4 v = *reinterpret_cast<float4*>(ws + row * 68 + (lane & 15) * 4);
                red_add_v4(outb + (size_t)o * CO + ncol, v.x, v.y, v.z, v.w);
            }
        }
        __syncwarp();
    }
}

// ===========================================================================
// BN (eval) + ReLU on output
// ===========================================================================
__global__ void bn_relu_kernel(float* __restrict__ buf,
                               const float* __restrict__ gamma,
                               const float* __restrict__ beta,
                               const float* __restrict__ mean,
                               const float* __restrict__ var) {
    int c = threadIdx.x;
    float s  = gamma[c] * rsqrtf(var[c] + BN_EPS);
    float sh = beta[c] - mean[c] * s;
    for (int row = blockIdx.x; row < NB; row += gridDim.x) {
        size_t idx = (size_t)row * CO + c;
        buf[idx] = fmaxf(fmaf(buf[idx], s, sh), 0.f);
    }
}

// ===========================================================================
extern "C" void kernel_launch(void* const* d_in, const int* in_sizes, int n_in,
                              void* d_out, int out_size) {
    const float* feats_a    = (const float*)d_in[0];
    const float* feats_b    = (const float*)d_in[1];
    const float* W_t        = (const float*)d_in[2];
    const float* bn_t_gamma = (const float*)d_in[3];
    const float* bn_t_beta  = (const float*)d_in[4];
    const float* bn_t_mean  = (const float*)d_in[5];
    const float* bn_t_var   = (const float*)d_in[6];
    const float* W_c        = (const float*)d_in[7];
    const float* bn_c_gamma = (const float*)d_in[8];
    const float* bn_c_beta  = (const float*)d_in[9];
    const float* bn_c_mean  = (const float*)d_in[10];
    const float* bn_c_var   = (const float*)d_in[11];
    const int*   in_map_t   = (const int*)d_in[12];
    const int*   out_map_t  = (const int*)d_in[13];
    const int*   in_map_c   = (const int*)d_in[14];
    const int*   out_map_c  = (const int*)d_in[15];
    float* out = (float*)d_out;

    cudaFuncSetAttribute(spconv_mma_kernel<CA, true>,
                         cudaFuncAttributeMaxDynamicSharedMemorySize, SMEM_TOTAL);
    cudaFuncSetAttribute(spconv_mma_kernel<CX, false>,
                         cudaFuncAttributeMaxDynamicSharedMemorySize, SMEM_TOTAL);

    void *wt, *wc, *gx, *gas, *gxs;
    cudaGetSymbolAddress(&wt, g_Wt);
    cudaGetSymbolAddress(&wc, g_Wc);
    cudaGetSymbolAddress(&gx, g_x);
    cudaGetSymbolAddress(&gas, g_as);
    cudaGetSymbolAddress(&gxs, g_xs);

    // 0) weight transpose + fp16 ; feats_a fp16 ; zero accumulators
    prep_w_kernel<CA><<<dim3(CO / 32, CA / 32, KT), dim3(32, 8)>>>(W_t, (__half*)wt);
    prep_w_kernel<CX><<<dim3(CO / 32, CX / 32, KC), dim3(32, 8)>>>(W_c, (__half*)wc);
    prep_a_kernel<<<NA, 64>>>(feats_a);
    {
        int n4 = (int)((size_t)NB * CO / 4);
        zero_f4_kernel<<<(n4 + 255) / 256, 256>>>((float*)gx, n4);
        zero_f4_kernel<<<(n4 + 255) / 256, 256>>>(out, n4);
    }

    // 1) transpose conv: g_as -> g_x (fp32 accum)
    {
        dim3 grid((MT + 127) / 128, 1, KT);
        spconv_mma_kernel<CA, true><<<grid, 256, SMEM_TOTAL>>>(
            (const __half*)gas, (const __half*)wt, in_map_t, out_map_t, nullptr, MT);
    }

    // 2) BN+ReLU + concat -> g_xs (fp16)
    bn_split_x_kernel<<<NB, 128>>>(feats_b, bn_t_gamma, bn_t_beta,
                                   bn_t_mean, bn_t_var);

    // 3) 3x3x3 conv: g_xs -> out
    {
        dim3 grid((MC + 127) / 128, 1, KC);
        spconv_mma_kernel<CX, false><<<grid, 256, SMEM_TOTAL>>>(
            (const __half*)gxs, (const __half*)wc, in_map_c, out_map_c, out, MC);
    }

    // 4) BN + ReLU on output
    bn_relu_kernel<<<2048, 256>>>(out, bn_c_gamma, bn_c_beta,
                                  bn_c_mean, bn_c_var);
}